// round 11
// baseline (speedup 1.0000x reference)
#include <cuda_runtime.h>
#include <cuda_bf16.h>
#include <cstdint>

#define NN      50000
#define NE      800000
#define NRELS   200
#define FB      148          // front-end blocks (1/SM, co-resident)
#define FT      1024         // front-end threads per block

// -------- scratch (device globals; allocation is forbidden) --------
__device__ int          g_cnt[NN];           // dst degree (re-zeroed by k_back each call)
__device__ int          g_off[NN + 1];       // global exclusive offsets
__device__ int          g_cur[NN];           // scatter cursors (consumed each call)
__device__ int          g_bsum[FB];
__device__ int          g_boff[FB];
__device__ unsigned int g_key[NE];           // (src | etype<<16) sorted by dst
__device__ float        g_rr[NRELS * 128];   // interleaved (rel, relB) per relation

// grid barrier state: generation flags grow monotonically (no reset needed)
__device__ unsigned int g_bar_cnt[4];
__device__ unsigned int g_bar_flag[4];

// -------- f32x2 helpers --------
#define FMA2(acc, a, b) \
    asm("fma.rn.f32x2 %0, %1, %2, %0;" : "+l"(acc) : "l"(a), "l"(b))
#define PACK_DUP(h2, h) \
    asm("mov.b64 %0, {%1, %1};" : "=l"(h2) : "f"(h))
#define UNPACK2(lo, hi, v) \
    asm("mov.b64 {%0, %1}, %2;" : "=f"(lo), "=f"(hi) : "l"(v))

// -------- software grid barrier (sense-reversal; FB co-resident blocks) --------
__device__ __forceinline__ void grid_sync(int i) {
    __threadfence();
    __syncthreads();
    if (threadIdx.x == 0) {
        unsigned sense = *(volatile unsigned*)&g_bar_flag[i];
        unsigned old = atomicAdd(&g_bar_cnt[i], 1u);
        if (old == (unsigned)(FB - 1)) {
            g_bar_cnt[i] = 0;
            __threadfence();
            atomicAdd(&g_bar_flag[i], 1u);   // release (generation++)
        } else {
            while (*(volatile unsigned*)&g_bar_flag[i] == sense) __nanosleep(64);
        }
        __threadfence();
    }
    __syncthreads();
}

// -------- K1: fused front-end: relB+hist -> scan -> boff -> globalize -> scatter --------
__global__ __launch_bounds__(FT) void k_front(const float* __restrict__ rel,
                                              const float* __restrict__ Wn,
                                              const int* __restrict__ src,
                                              const int* __restrict__ dst,
                                              const int* __restrict__ et, int E) {
    __shared__ int tmp[FT];
    int b = blockIdx.x, tid = threadIdx.x;
    int gid = b * FT + tid;
    const int nthr = FB * FT;

    // ---- phase 0: relB table + dst degree histogram ----
    if (gid < NRELS * 64) {
        int t = gid >> 6, j = gid & 63;
        float s = 0.0f;
        #pragma unroll 8
        for (int k = 0; k < 64; k++)
            s += rel[t * 64 + k] * (Wn[k * 64 + j] + Wn[(192 + k) * 64 + j]);
        int base = t * 128 + (j >> 1) * 4 + (j & 1);
        g_rr[base]     = rel[t * 64 + j];
        g_rr[base + 2] = s;
    }
    int n4 = E >> 2;
    {
        const int4* d4 = (const int4*)dst;
        for (int j = gid; j < n4; j += nthr) {
            int4 v = d4[j];
            atomicAdd(&g_cnt[v.x], 1);
            atomicAdd(&g_cnt[v.y], 1);
            atomicAdd(&g_cnt[v.z], 1);
            atomicAdd(&g_cnt[v.w], 1);
        }
        if (gid < (E & 3)) atomicAdd(&g_cnt[dst[(n4 << 2) + gid]], 1);
    }
    grid_sync(0);

    // ---- phase 1a: per-block local exclusive scan over FT counts ----
    int v = (gid < NN) ? g_cnt[gid] : 0;
    tmp[tid] = v;
    __syncthreads();
    #pragma unroll
    for (int d = 1; d < FT; d <<= 1) {
        int t = (tid >= d) ? tmp[tid - d] : 0;
        __syncthreads();
        tmp[tid] += t;
        __syncthreads();
    }
    int loc = tmp[tid] - v;               // local exclusive offset (register)
    if (tid == FT - 1) g_bsum[b] = tmp[FT - 1];
    grid_sync(1);

    // ---- phase 1b: block 0 scans the FB block sums ----
    if (b == 0) {
        int vv = (tid < FB) ? g_bsum[tid] : 0;
        if (tid < 256) tmp[tid] = vv;
        __syncthreads();
        #pragma unroll
        for (int d = 1; d < 256; d <<= 1) {
            int t = (tid >= d && tid < 256) ? tmp[tid - d] : 0;
            __syncthreads();
            if (tid < 256) tmp[tid] += t;
            __syncthreads();
        }
        if (tid < FB) g_boff[tid] = tmp[tid] - vv;
        if (tid == 0) g_off[NN] = E;
    }
    grid_sync(2);

    // ---- phase 1c: globalize offsets + init cursors ----
    if (gid < NN) {
        int off = loc + g_boff[b];
        g_off[gid] = off;
        g_cur[gid] = off;
    }
    grid_sync(3);

    // ---- phase 2: counting-sort scatter by dst ----
    {
        const int4* s4 = (const int4*)src;
        const int4* d4 = (const int4*)dst;
        const int4* t4 = (const int4*)et;
        for (int j = gid; j < n4; j += nthr) {
            int4 s = s4[j];
            int4 d = d4[j];
            int4 t = t4[j];
            int p0 = atomicAdd(&g_cur[d.x], 1);
            int p1 = atomicAdd(&g_cur[d.y], 1);
            int p2 = atomicAdd(&g_cur[d.z], 1);
            int p3 = atomicAdd(&g_cur[d.w], 1);
            g_key[p0] = (unsigned)s.x | ((unsigned)t.x << 16);
            g_key[p1] = (unsigned)s.y | ((unsigned)t.y << 16);
            g_key[p2] = (unsigned)s.z | ((unsigned)t.z << 16);
            g_key[p3] = (unsigned)s.w | ((unsigned)t.w << 16);
        }
        if (gid < (E & 3)) {
            int e = (n4 << 2) + gid;
            int p = atomicAdd(&g_cur[dst[e]], 1);
            g_key[p] = (unsigned)src[e] | ((unsigned)et[e] << 16);
        }
    }
}

// -------- K2: fused backend: per-warp aggregation into SMEM + block GEMM --------
// smem: W13s[4096] W2s[4096] LWs[4096] As[32*65] Bs[32*65] Cs[32*65] Fs[32*65]
#define TS 65
#define BSMEM ((3 * 4096 + 4 * 32 * TS) * 4)

__global__ __launch_bounds__(256) void k_back(const float* __restrict__ feat,
                                              const float* __restrict__ Wn,
                                              const float* __restrict__ LW,
                                              float* __restrict__ out, int N) {
    extern __shared__ float smem[];
    float* W13s = smem;
    float* W2s  = smem + 4096;
    float* LWs  = smem + 8192;
    float* As   = smem + 12288;
    float* Bs   = As + 32 * TS;
    float* Cs   = Bs + 32 * TS;
    float* Fs   = Cs + 32 * TS;

    int tid = threadIdx.x;
    int wid = tid >> 5, lane = tid & 31;
    int n0 = blockIdx.x * 32;

    // issue weight loads early; they overlap the edge-gather latency below
    for (int idx = tid; idx < 4096; idx += 256) {
        W13s[idx] = Wn[idx] + Wn[8192 + idx];
        W2s[idx]  = Wn[4096 + idx];
        LWs[idx]  = LW[idx];
    }

    // ---- phase A: each warp aggregates 4 nodes into SMEM rows ----
    const float2* f2  = (const float2*)feat;
    const float4* rr4 = (const float4*)g_rr;

    #pragma unroll
    for (int q = 0; q < 4; q++) {
        int local = wid * 4 + q;
        int node = n0 + local;
        float ax0 = 0.f, ay0 = 0.f, bx0 = 0.f, by0 = 0.f, cx0 = 0.f, cy0 = 0.f;
        float ax1 = 0.f, ay1 = 0.f, bx1 = 0.f, by1 = 0.f, cx1 = 0.f, cy1 = 0.f;
        int deg = 0;
        if (node < N) {
            int beg = g_off[node], end = g_off[node + 1];
            deg = end - beg;
            if (lane == 0) g_cnt[node] = 0;     // re-zero for next replay

            int i = beg;
            if (deg & 1) {
                unsigned k = g_key[i++];
                float2 h = f2[(k & 0xffffu) * 32 + lane];
                float4 qq = rr4[(k >> 16) * 32 + lane];
                ax0 += h.x;  ay0 += h.y;
                bx0 = fmaf(h.x, qq.x, bx0);
                by0 = fmaf(h.y, qq.y, by0);
                cx0 += qq.z; cy0 += qq.w;
            }
            if (i < end) {
                unsigned k0 = g_key[i];
                unsigned k1 = g_key[i + 1];
                for (; i < end; i += 2) {
                    bool more = (i + 2) < end;
                    unsigned m0 = more ? g_key[i + 2] : k0;
                    unsigned m1 = more ? g_key[i + 3] : k1;

                    float2 h0 = f2[(k0 & 0xffffu) * 32 + lane];
                    float4 q0 = rr4[(k0 >> 16) * 32 + lane];
                    float2 h1 = f2[(k1 & 0xffffu) * 32 + lane];
                    float4 q1 = rr4[(k1 >> 16) * 32 + lane];

                    ax0 += h0.x;  ay0 += h0.y;
                    bx0 = fmaf(h0.x, q0.x, bx0);
                    by0 = fmaf(h0.y, q0.y, by0);
                    cx0 += q0.z;  cy0 += q0.w;

                    ax1 += h1.x;  ay1 += h1.y;
                    bx1 = fmaf(h1.x, q1.x, bx1);
                    by1 = fmaf(h1.y, q1.y, by1);
                    cx1 += q1.z;  cy1 += q1.w;

                    k0 = m0; k1 = m1;
                }
            }
        }
        float inv = 1.0f / fmaxf((float)deg, 1.0f);
        float* ar = &As[local * TS];
        float* br = &Bs[local * TS];
        float* cr = &Cs[local * TS];
        ar[2 * lane]     = (ax0 + ax1) * inv;
        ar[2 * lane + 1] = (ay0 + ay1) * inv;
        br[2 * lane]     = (bx0 + bx1) * inv;
        br[2 * lane + 1] = (by0 + by1) * inv;
        cr[2 * lane]     = (cx0 + cx1) * inv;
        cr[2 * lane + 1] = (cy0 + cy1) * inv;
    }

    // feat tile for the loop GEMM (32 nodes x 64 floats)
    #pragma unroll
    for (int p = 0; p < 2; p++) {
        int idx = p * 256 + tid;          // 0..511 float4 slots
        int e = idx >> 4, c4 = idx & 15;
        int node = n0 + e;
        float4 v = make_float4(0.f, 0.f, 0.f, 0.f);
        if (node < N) v = *(const float4*)&feat[(size_t)node * 64 + c4 * 4];
        float* hp = &Fs[e * TS + c4 * 4];
        hp[0] = v.x; hp[1] = v.y; hp[2] = v.z; hp[3] = v.w;
    }
    __syncthreads();

    // ---- phase B: out = A@W13 + B@W2 + C + F@LW ----
    int ty = tid >> 3, tx = tid & 7, jj = tx * 8;
    int node = n0 + ty;

    unsigned long long a0 = 0, a1 = 0, a2 = 0, a3 = 0;
    #pragma unroll 4
    for (int k = 0; k < 64; k++) {
        float la = As[ty * TS + k];
        float lb = Bs[ty * TS + k];
        float lf = Fs[ty * TS + k];
        unsigned long long la2, lb2, lf2;
        PACK_DUP(la2, la); PACK_DUP(lb2, lb); PACK_DUP(lf2, lf);

        const float* w13 = &W13s[(k << 6) + jj];
        const float* w2  = &W2s[(k << 6) + jj];
        const float* lw  = &LWs[(k << 6) + jj];
        ulonglong2 wA = *reinterpret_cast<const ulonglong2*>(w13);
        ulonglong2 wB = *reinterpret_cast<const ulonglong2*>(w13 + 4);
        ulonglong2 vA = *reinterpret_cast<const ulonglong2*>(w2);
        ulonglong2 vB = *reinterpret_cast<const ulonglong2*>(w2 + 4);
        ulonglong2 uA = *reinterpret_cast<const ulonglong2*>(lw);
        ulonglong2 uB = *reinterpret_cast<const ulonglong2*>(lw + 4);

        FMA2(a0, la2, wA.x); FMA2(a1, la2, wA.y); FMA2(a2, la2, wB.x); FMA2(a3, la2, wB.y);
        FMA2(a0, lb2, vA.x); FMA2(a1, lb2, vA.y); FMA2(a2, lb2, vB.x); FMA2(a3, lb2, vB.y);
        FMA2(a0, lf2, uA.x); FMA2(a1, lf2, uA.y); FMA2(a2, lf2, uB.x); FMA2(a3, lf2, uB.y);
    }

    if (node < N) {
        float v0, v1, v2, v3, v4, v5, v6, v7;
        UNPACK2(v0, v1, a0); UNPACK2(v2, v3, a1);
        UNPACK2(v4, v5, a2); UNPACK2(v6, v7, a3);
        const float* cr = &Cs[ty * TS + jj];
        float* p = out + (size_t)node * 64 + jj;
        *(float4*)p       = make_float4(v0 + cr[0], v1 + cr[1], v2 + cr[2], v3 + cr[3]);
        *(float4*)(p + 4) = make_float4(v4 + cr[4], v5 + cr[5], v6 + cr[6], v7 + cr[7]);
    }
}

// -------- launch --------
extern "C" void kernel_launch(void* const* d_in, const int* in_sizes, int n_in,
                              void* d_out, int out_size) {
    const float* feat = (const float*)d_in[0];
    const float* rel  = (const float*)d_in[1];
    const float* Wn   = (const float*)d_in[2];
    const float* LW   = (const float*)d_in[3];
    const int*   src  = (const int*)d_in[4];
    const int*   dst  = (const int*)d_in[5];
    const int*   et   = (const int*)d_in[6];
    float* out = (float*)d_out;

    int E = in_sizes[4];
    int N = in_sizes[0] / 64;

    cudaFuncSetAttribute(k_back, cudaFuncAttributeMaxDynamicSharedMemorySize, BSMEM);

    k_front<<<FB, FT>>>(rel, Wn, src, dst, et, E);               // 0
    k_back<<<(N + 31) / 32, 256, BSMEM>>>(feat, Wn, LW, out, N); // 1
}

// round 12
// speedup vs baseline: 1.0725x; 1.0725x over previous
#include <cuda_runtime.h>
#include <cuda_bf16.h>
#include <cstdint>

#define NN      50000
#define NE      800000
#define NRELS   200
#define FB      148          // front-end blocks (1/SM, co-resident)
#define FT      1024         // front-end threads per block

// -------- scratch (device globals; allocation is forbidden) --------
__device__ int          g_cnt[NN];           // dst degree (re-zeroed by k_agg each call)
__device__ int          g_off[NN + 1];       // global exclusive offsets
__device__ int          g_cur[NN];           // scatter cursors (consumed each call)
__device__ int          g_bsum[FB];
__device__ int          g_boff[FB];
__device__ unsigned int g_key[NE];           // (src | etype<<16) sorted by dst
__device__ float        g_rr[NRELS * 128];   // interleaved (rel, relB) per relation
__device__ float        g_A[NN * 64];
__device__ float        g_B[NN * 64];
__device__ float        g_C[NN * 64];

// grid barrier state: generation flags grow monotonically (no reset needed)
__device__ unsigned int g_bar_cnt[4];
__device__ unsigned int g_bar_flag[4];

// -------- f32x2 helpers --------
#define FMA2(acc, a, b) \
    asm("fma.rn.f32x2 %0, %1, %2, %0;" : "+l"(acc) : "l"(a), "l"(b))
#define ADD2(acc, v) \
    asm("add.rn.f32x2 %0, %0, %1;" : "+l"(acc) : "l"(v))
#define PACK_DUP(h2, h) \
    asm("mov.b64 %0, {%1, %1};" : "=l"(h2) : "f"(h))
#define UNPACK2(lo, hi, v) \
    asm("mov.b64 {%0, %1}, %2;" : "=f"(lo), "=f"(hi) : "l"(v))

// -------- software grid barrier (sense-reversal; FB co-resident blocks) --------
__device__ __forceinline__ void grid_sync(int i) {
    __threadfence();
    __syncthreads();
    if (threadIdx.x == 0) {
        unsigned sense = *(volatile unsigned*)&g_bar_flag[i];
        unsigned old = atomicAdd(&g_bar_cnt[i], 1u);
        if (old == (unsigned)(FB - 1)) {
            g_bar_cnt[i] = 0;
            __threadfence();
            atomicAdd(&g_bar_flag[i], 1u);   // release (generation++)
        } else {
            while (*(volatile unsigned*)&g_bar_flag[i] == sense) __nanosleep(64);
        }
        __threadfence();
    }
    __syncthreads();
}

// -------- K1: fused front-end: relB+hist -> scan -> boff -> globalize -> scatter --------
__global__ __launch_bounds__(FT) void k_front(const float* __restrict__ rel,
                                              const float* __restrict__ Wn,
                                              const int* __restrict__ src,
                                              const int* __restrict__ dst,
                                              const int* __restrict__ et, int E) {
    __shared__ int tmp[FT];
    int b = blockIdx.x, tid = threadIdx.x;
    int gid = b * FT + tid;
    const int nthr = FB * FT;

    // ---- phase 0: relB table + dst degree histogram ----
    if (gid < NRELS * 64) {
        int t = gid >> 6, j = gid & 63;
        float s = 0.0f;
        #pragma unroll 8
        for (int k = 0; k < 64; k++)
            s += rel[t * 64 + k] * (Wn[k * 64 + j] + Wn[(192 + k) * 64 + j]);
        int base = t * 128 + (j >> 1) * 4 + (j & 1);
        g_rr[base]     = rel[t * 64 + j];
        g_rr[base + 2] = s;
    }
    int n4 = E >> 2;
    {
        const int4* d4 = (const int4*)dst;
        for (int j = gid; j < n4; j += nthr) {
            int4 v = d4[j];
            atomicAdd(&g_cnt[v.x], 1);
            atomicAdd(&g_cnt[v.y], 1);
            atomicAdd(&g_cnt[v.z], 1);
            atomicAdd(&g_cnt[v.w], 1);
        }
        if (gid < (E & 3)) atomicAdd(&g_cnt[dst[(n4 << 2) + gid]], 1);
    }
    grid_sync(0);

    // ---- phase 1a: per-block local exclusive scan over FT counts ----
    int v = (gid < NN) ? g_cnt[gid] : 0;
    tmp[tid] = v;
    __syncthreads();
    #pragma unroll
    for (int d = 1; d < FT; d <<= 1) {
        int t = (tid >= d) ? tmp[tid - d] : 0;
        __syncthreads();
        tmp[tid] += t;
        __syncthreads();
    }
    int loc = tmp[tid] - v;               // local exclusive offset (register)
    if (tid == FT - 1) g_bsum[b] = tmp[FT - 1];
    grid_sync(1);

    // ---- phase 1b: block 0 scans the FB block sums ----
    if (b == 0) {
        int vv = (tid < FB) ? g_bsum[tid] : 0;
        if (tid < 256) tmp[tid] = vv;
        __syncthreads();
        #pragma unroll
        for (int d = 1; d < 256; d <<= 1) {
            int t = (tid >= d && tid < 256) ? tmp[tid - d] : 0;
            __syncthreads();
            if (tid < 256) tmp[tid] += t;
            __syncthreads();
        }
        if (tid < FB) g_boff[tid] = tmp[tid] - vv;
        if (tid == 0) g_off[NN] = E;
    }
    grid_sync(2);

    // ---- phase 1c: globalize offsets + init cursors ----
    if (gid < NN) {
        int off = loc + g_boff[b];
        g_off[gid] = off;
        g_cur[gid] = off;
    }
    grid_sync(3);

    // ---- phase 2: counting-sort scatter by dst ----
    {
        const int4* s4 = (const int4*)src;
        const int4* d4 = (const int4*)dst;
        const int4* t4 = (const int4*)et;
        for (int j = gid; j < n4; j += nthr) {
            int4 s = s4[j];
            int4 d = d4[j];
            int4 t = t4[j];
            int p0 = atomicAdd(&g_cur[d.x], 1);
            int p1 = atomicAdd(&g_cur[d.y], 1);
            int p2 = atomicAdd(&g_cur[d.z], 1);
            int p3 = atomicAdd(&g_cur[d.w], 1);
            g_key[p0] = (unsigned)s.x | ((unsigned)t.x << 16);
            g_key[p1] = (unsigned)s.y | ((unsigned)t.y << 16);
            g_key[p2] = (unsigned)s.z | ((unsigned)t.z << 16);
            g_key[p3] = (unsigned)s.w | ((unsigned)t.w << 16);
        }
        if (gid < (E & 3)) {
            int e = (n4 << 2) + gid;
            int p = atomicAdd(&g_cur[dst[e]], 1);
            g_key[p] = (unsigned)src[e] | ((unsigned)et[e] << 16);
        }
    }
}

// -------- K2: per-dst aggregation (warp/node, 2-edge unroll, packed f32x2 math) --------
__global__ __launch_bounds__(256) void k_agg(const float* __restrict__ feat) {
    int w = (blockIdx.x * 256 + threadIdx.x) >> 5;
    if (w >= NN) return;
    int lane = threadIdx.x & 31;
    int beg = g_off[w], end = g_off[w + 1];
    if (lane == 0) g_cnt[w] = 0;      // re-zero for next replay (deterministic)

    const unsigned long long* f8  = (const unsigned long long*)feat;   // 32 packs / row
    const ulonglong2*         rr8 = (const ulonglong2*)g_rr;           // .x=(r pair) .y=(relB pair)

    unsigned long long A0 = 0ull, B0 = 0ull, C0 = 0ull;   // 0ull == (0.f, 0.f)
    unsigned long long A1 = 0ull, B1 = 0ull, C1 = 0ull;

    int i = beg;
    if ((end - beg) & 1) {                        // peel odd edge
        unsigned k = g_key[i++];
        unsigned long long h = f8[(k & 0xffffu) * 32 + lane];
        ulonglong2 q = rr8[(k >> 16) * 32 + lane];
        ADD2(A0, h);
        FMA2(B0, h, q.x);
        ADD2(C0, q.y);
    }
    if (i < end) {
        unsigned k0 = g_key[i];
        unsigned k1 = g_key[i + 1];
        for (; i < end; i += 2) {
            bool more = (i + 2) < end;
            unsigned n0 = more ? g_key[i + 2] : k0;
            unsigned n1 = more ? g_key[i + 3] : k1;

            unsigned long long h0 = f8[(k0 & 0xffffu) * 32 + lane];
            ulonglong2 q0 = rr8[(k0 >> 16) * 32 + lane];
            unsigned long long h1 = f8[(k1 & 0xffffu) * 32 + lane];
            ulonglong2 q1 = rr8[(k1 >> 16) * 32 + lane];

            ADD2(A0, h0);
            FMA2(B0, h0, q0.x);
            ADD2(C0, q0.y);

            ADD2(A1, h1);
            FMA2(B1, h1, q1.x);
            ADD2(C1, q1.y);

            k0 = n0; k1 = n1;
        }
    }

    float inv = 1.0f / fmaxf((float)(end - beg), 1.0f);
    float ax0, ay0, ax1, ay1, bx0, by0, bx1, by1, cx0, cy0, cx1, cy1;
    UNPACK2(ax0, ay0, A0); UNPACK2(ax1, ay1, A1);
    UNPACK2(bx0, by0, B0); UNPACK2(bx1, by1, B1);
    UNPACK2(cx0, cy0, C0); UNPACK2(cx1, cy1, C1);

    int o = w * 32 + lane;
    ((float2*)g_A)[o] = make_float2((ax0 + ax1) * inv, (ay0 + ay1) * inv);
    ((float2*)g_B)[o] = make_float2((bx0 + bx1) * inv, (by0 + by1) * inv);
    ((float2*)g_C)[o] = make_float2((cx0 + cx1) * inv, (cy0 + cy1) * inv);
}

// -------- K3: out = A@W13 + B@W2 + C + feat@LW  (32 nodes / block, 256 thr) --------
#define TS 65
#define FSMEM ((3 * 4096 + 3 * 32 * TS) * 4)

__global__ __launch_bounds__(256) void k_final(const float* __restrict__ feat,
                                               const float* __restrict__ Wn,
                                               const float* __restrict__ LW,
                                               float* __restrict__ out, int N) {
    extern __shared__ float smem[];
    float* W13s = smem;                 // 4096
    float* W2s  = smem + 4096;          // 4096
    float* LWs  = smem + 8192;          // 4096
    float* As   = smem + 12288;         // 32*65
    float* Bs   = As + 32 * TS;
    float* Fs   = Bs + 32 * TS;

    int tid = threadIdx.x;
    for (int idx = tid; idx < 4096; idx += 256) {
        W13s[idx] = Wn[idx] + Wn[8192 + idx];
        W2s[idx]  = Wn[4096 + idx];
        LWs[idx]  = LW[idx];
    }

    int n0 = blockIdx.x * 32;
    #pragma unroll
    for (int p = 0; p < 6; p++) {
        int idx = p * 256 + tid;
        int mat = idx >> 9;
        int slot = idx & 511;
        int e = slot >> 4, c4 = slot & 15;
        int node = n0 + e;
        const float* srcp = (mat == 0) ? g_A : (mat == 1) ? g_B : feat;
        float* dstp = (mat == 0) ? As : (mat == 1) ? Bs : Fs;
        float4 v = make_float4(0.f, 0.f, 0.f, 0.f);
        if (node < N) v = *(const float4*)&srcp[(size_t)node * 64 + c4 * 4];
        float* hp = &dstp[e * TS + c4 * 4];
        hp[0] = v.x; hp[1] = v.y; hp[2] = v.z; hp[3] = v.w;
    }
    __syncthreads();

    int ty = tid >> 3, tx = tid & 7, jj = tx * 8;
    int node = n0 + ty;

    unsigned long long a0 = 0, a1 = 0, a2 = 0, a3 = 0;
    #pragma unroll 4
    for (int k = 0; k < 64; k++) {
        float la = As[ty * TS + k];
        float lb = Bs[ty * TS + k];
        float lf = Fs[ty * TS + k];
        unsigned long long la2, lb2, lf2;
        PACK_DUP(la2, la); PACK_DUP(lb2, lb); PACK_DUP(lf2, lf);

        const float* w13 = &W13s[(k << 6) + jj];
        const float* w2  = &W2s[(k << 6) + jj];
        const float* lw  = &LWs[(k << 6) + jj];
        ulonglong2 wA = *reinterpret_cast<const ulonglong2*>(w13);
        ulonglong2 wB = *reinterpret_cast<const ulonglong2*>(w13 + 4);
        ulonglong2 vA = *reinterpret_cast<const ulonglong2*>(w2);
        ulonglong2 vB = *reinterpret_cast<const ulonglong2*>(w2 + 4);
        ulonglong2 uA = *reinterpret_cast<const ulonglong2*>(lw);
        ulonglong2 uB = *reinterpret_cast<const ulonglong2*>(lw + 4);

        FMA2(a0, la2, wA.x); FMA2(a1, la2, wA.y); FMA2(a2, la2, wB.x); FMA2(a3, la2, wB.y);
        FMA2(a0, lb2, vA.x); FMA2(a1, lb2, vA.y); FMA2(a2, lb2, vB.x); FMA2(a3, lb2, vB.y);
        FMA2(a0, lf2, uA.x); FMA2(a1, lf2, uA.y); FMA2(a2, lf2, uB.x); FMA2(a3, lf2, uB.y);
    }

    if (node < N) {
        float4 c0 = *(const float4*)&g_C[(size_t)node * 64 + jj];
        float4 c1 = *(const float4*)&g_C[(size_t)node * 64 + jj + 4];
        float v0, v1, v2, v3, v4, v5, v6, v7;
        UNPACK2(v0, v1, a0); UNPACK2(v2, v3, a1);
        UNPACK2(v4, v5, a2); UNPACK2(v6, v7, a3);
        float* p = out + (size_t)node * 64 + jj;
        *(float4*)p       = make_float4(v0 + c0.x, v1 + c0.y, v2 + c0.z, v3 + c0.w);
        *(float4*)(p + 4) = make_float4(v4 + c1.x, v5 + c1.y, v6 + c1.z, v7 + c1.w);
    }
}

// -------- launch --------
extern "C" void kernel_launch(void* const* d_in, const int* in_sizes, int n_in,
                              void* d_out, int out_size) {
    const float* feat = (const float*)d_in[0];
    const float* rel  = (const float*)d_in[1];
    const float* Wn   = (const float*)d_in[2];
    const float* LW   = (const float*)d_in[3];
    const int*   src  = (const int*)d_in[4];
    const int*   dst  = (const int*)d_in[5];
    const int*   et   = (const int*)d_in[6];
    float* out = (float*)d_out;

    int E = in_sizes[4];
    int N = in_sizes[0] / 64;

    cudaFuncSetAttribute(k_final, cudaFuncAttributeMaxDynamicSharedMemorySize, FSMEM);

    k_front<<<FB, FT>>>(rel, Wn, src, dst, et, E);                   // 0
    k_agg<<<(NN * 32 + 255) / 256, 256>>>(feat);                     // 1
    k_final<<<(N + 31) / 32, 256, FSMEM>>>(feat, Wn, LW, out, N);    // 2
}

// round 13
// speedup vs baseline: 1.3955x; 1.3012x over previous
#include <cuda_runtime.h>
#include <cuda_bf16.h>
#include <cstdint>

#define NN      50000
#define NE      800000
#define NRELS   200
#define FB      148          // front-end blocks (1/SM, co-resident)
#define FT      1024         // front-end threads per block

// -------- scratch (device globals; allocation is forbidden) --------
__device__ int          g_cnt[NN];           // dst degree (re-zeroed by k_agg each call)
__device__ int          g_off[NN + 1];       // global exclusive offsets
__device__ int          g_cur[NN];           // scatter cursors (consumed each call)
__device__ int          g_bsum[FB];
__device__ int          g_boff[FB];
__device__ unsigned int g_key[NE];           // (src | etype<<16) sorted by dst
__device__ float        g_rr[NRELS * 128];   // interleaved (rel, relB) per relation
__device__ float        g_A[NN * 64];
__device__ float        g_B[NN * 64];
__device__ float        g_C[NN * 64];

// grid barrier state: generation flags grow monotonically (no reset needed)
__device__ unsigned int g_bar_cnt[4];
__device__ unsigned int g_bar_flag[4];

// -------- f32x2 helpers --------
#define FMA2(acc, a, b) \
    asm("fma.rn.f32x2 %0, %1, %2, %0;" : "+l"(acc) : "l"(a), "l"(b))
#define ADD2(acc, v) \
    asm("add.rn.f32x2 %0, %0, %1;" : "+l"(acc) : "l"(v))
#define PACK_DUP(h2, h) \
    asm("mov.b64 %0, {%1, %1};" : "=l"(h2) : "f"(h))
#define UNPACK2(lo, hi, v) \
    asm("mov.b64 {%0, %1}, %2;" : "=f"(lo), "=f"(hi) : "l"(v))

// -------- software grid barrier (sense-reversal; FB co-resident blocks) --------
__device__ __forceinline__ void grid_sync(int i) {
    __threadfence();
    __syncthreads();
    if (threadIdx.x == 0) {
        unsigned sense = *(volatile unsigned*)&g_bar_flag[i];
        unsigned old = atomicAdd(&g_bar_cnt[i], 1u);
        if (old == (unsigned)(FB - 1)) {
            g_bar_cnt[i] = 0;
            __threadfence();
            atomicAdd(&g_bar_flag[i], 1u);   // release (generation++)
        } else {
            while (*(volatile unsigned*)&g_bar_flag[i] == sense) __nanosleep(64);
        }
        __threadfence();
    }
    __syncthreads();
}

// -------- K1: fused front-end: relB+hist -> scan -> boff -> globalize -> scatter --------
__global__ __launch_bounds__(FT) void k_front(const float* __restrict__ rel,
                                              const float* __restrict__ Wn,
                                              const int* __restrict__ src,
                                              const int* __restrict__ dst,
                                              const int* __restrict__ et, int E) {
    __shared__ int tmp[FT];
    int b = blockIdx.x, tid = threadIdx.x;
    int gid = b * FT + tid;
    const int nthr = FB * FT;

    // ---- phase 0: relB table + dst degree histogram ----
    if (gid < NRELS * 64) {
        int t = gid >> 6, j = gid & 63;
        float s = 0.0f;
        #pragma unroll 8
        for (int k = 0; k < 64; k++)
            s += rel[t * 64 + k] * (Wn[k * 64 + j] + Wn[(192 + k) * 64 + j]);
        int base = t * 128 + (j >> 1) * 4 + (j & 1);
        g_rr[base]     = rel[t * 64 + j];
        g_rr[base + 2] = s;
    }
    int n4 = E >> 2;
    {
        const int4* d4 = (const int4*)dst;
        for (int j = gid; j < n4; j += nthr) {
            int4 v = d4[j];
            atomicAdd(&g_cnt[v.x], 1);
            atomicAdd(&g_cnt[v.y], 1);
            atomicAdd(&g_cnt[v.z], 1);
            atomicAdd(&g_cnt[v.w], 1);
        }
        if (gid < (E & 3)) atomicAdd(&g_cnt[dst[(n4 << 2) + gid]], 1);
    }
    grid_sync(0);

    // ---- phase 1a: per-block local exclusive scan over FT counts ----
    int v = (gid < NN) ? g_cnt[gid] : 0;
    tmp[tid] = v;
    __syncthreads();
    #pragma unroll
    for (int d = 1; d < FT; d <<= 1) {
        int t = (tid >= d) ? tmp[tid - d] : 0;
        __syncthreads();
        tmp[tid] += t;
        __syncthreads();
    }
    int loc = tmp[tid] - v;               // local exclusive offset (register)
    if (tid == FT - 1) g_bsum[b] = tmp[FT - 1];
    grid_sync(1);

    // ---- phase 1b: block 0 scans the FB block sums ----
    if (b == 0) {
        int vv = (tid < FB) ? g_bsum[tid] : 0;
        if (tid < 256) tmp[tid] = vv;
        __syncthreads();
        #pragma unroll
        for (int d = 1; d < 256; d <<= 1) {
            int t = (tid >= d && tid < 256) ? tmp[tid - d] : 0;
            __syncthreads();
            if (tid < 256) tmp[tid] += t;
            __syncthreads();
        }
        if (tid < FB) g_boff[tid] = tmp[tid] - vv;
        if (tid == 0) g_off[NN] = E;
    }
    grid_sync(2);

    // ---- phase 1c: globalize offsets + init cursors ----
    if (gid < NN) {
        int off = loc + g_boff[b];
        g_off[gid] = off;
        g_cur[gid] = off;
    }
    grid_sync(3);

    // ---- phase 2: counting-sort scatter by dst ----
    {
        const int4* s4 = (const int4*)src;
        const int4* d4 = (const int4*)dst;
        const int4* t4 = (const int4*)et;
        for (int j = gid; j < n4; j += nthr) {
            int4 s = s4[j];
            int4 d = d4[j];
            int4 t = t4[j];
            int p0 = atomicAdd(&g_cur[d.x], 1);
            int p1 = atomicAdd(&g_cur[d.y], 1);
            int p2 = atomicAdd(&g_cur[d.z], 1);
            int p3 = atomicAdd(&g_cur[d.w], 1);
            g_key[p0] = (unsigned)s.x | ((unsigned)t.x << 16);
            g_key[p1] = (unsigned)s.y | ((unsigned)t.y << 16);
            g_key[p2] = (unsigned)s.z | ((unsigned)t.z << 16);
            g_key[p3] = (unsigned)s.w | ((unsigned)t.w << 16);
        }
        if (gid < (E & 3)) {
            int e = (n4 << 2) + gid;
            int p = atomicAdd(&g_cur[dst[e]], 1);
            g_key[p] = (unsigned)src[e] | ((unsigned)et[e] << 16);
        }
    }
}

// -------- K2: per-dst aggregation (warp/node, 2-edge unroll, packed f32x2 math) --------
__global__ __launch_bounds__(256) void k_agg(const float* __restrict__ feat) {
    int w = (blockIdx.x * 256 + threadIdx.x) >> 5;
    if (w >= NN) return;
    int lane = threadIdx.x & 31;
    int beg = g_off[w], end = g_off[w + 1];
    if (lane == 0) g_cnt[w] = 0;      // re-zero for next replay (deterministic)

    const unsigned long long* f8  = (const unsigned long long*)feat;   // 32 packs / row
    const ulonglong2*         rr8 = (const ulonglong2*)g_rr;           // .x=(r pair) .y=(relB pair)

    unsigned long long A0 = 0ull, B0 = 0ull, C0 = 0ull;
    unsigned long long A1 = 0ull, B1 = 0ull, C1 = 0ull;

    int i = beg;
    if ((end - beg) & 1) {                        // peel odd edge
        unsigned k = g_key[i++];
        unsigned long long h = f8[(k & 0xffffu) * 32 + lane];
        ulonglong2 q = rr8[(k >> 16) * 32 + lane];
        ADD2(A0, h);
        FMA2(B0, h, q.x);
        ADD2(C0, q.y);
    }
    if (i < end) {
        unsigned k0 = g_key[i];
        unsigned k1 = g_key[i + 1];
        for (; i < end; i += 2) {
            bool more = (i + 2) < end;
            unsigned n0 = more ? g_key[i + 2] : k0;
            unsigned n1 = more ? g_key[i + 3] : k1;

            unsigned long long h0 = f8[(k0 & 0xffffu) * 32 + lane];
            ulonglong2 q0 = rr8[(k0 >> 16) * 32 + lane];
            unsigned long long h1 = f8[(k1 & 0xffffu) * 32 + lane];
            ulonglong2 q1 = rr8[(k1 >> 16) * 32 + lane];

            ADD2(A0, h0);
            FMA2(B0, h0, q0.x);
            ADD2(C0, q0.y);

            ADD2(A1, h1);
            FMA2(B1, h1, q1.x);
            ADD2(C1, q1.y);

            k0 = n0; k1 = n1;
        }
    }

    float inv = 1.0f / fmaxf((float)(end - beg), 1.0f);
    float ax0, ay0, ax1, ay1, bx0, by0, bx1, by1, cx0, cy0, cx1, cy1;
    UNPACK2(ax0, ay0, A0); UNPACK2(ax1, ay1, A1);
    UNPACK2(bx0, by0, B0); UNPACK2(bx1, by1, B1);
    UNPACK2(cx0, cy0, C0); UNPACK2(cx1, cy1, C1);

    int o = w * 32 + lane;
    ((float2*)g_A)[o] = make_float2((ax0 + ax1) * inv, (ay0 + ay1) * inv);
    ((float2*)g_B)[o] = make_float2((bx0 + bx1) * inv, (by0 + by1) * inv);
    ((float2*)g_C)[o] = make_float2((cx0 + cx1) * inv, (cy0 + cy1) * inv);
}

// -------- K3: out = A@W13 + B@W2 + C + feat@LW --------
// 64 nodes / block, 256 threads, 2 nodes per thread: halves SMEM weight traffic/node
#define TS 65
#define FN 64
#define FSMEM ((3 * 4096 + 3 * FN * TS) * 4)

__global__ __launch_bounds__(256) void k_final(const float* __restrict__ feat,
                                               const float* __restrict__ Wn,
                                               const float* __restrict__ LW,
                                               float* __restrict__ out, int N) {
    extern __shared__ float smem[];
    float* W13s = smem;                 // 4096
    float* W2s  = smem + 4096;          // 4096
    float* LWs  = smem + 8192;          // 4096
    float* As   = smem + 12288;         // 64*65
    float* Bs   = As + FN * TS;
    float* Fs   = Bs + FN * TS;

    int tid = threadIdx.x;
    for (int idx = tid; idx < 4096; idx += 256) {
        W13s[idx] = Wn[idx] + Wn[8192 + idx];
        W2s[idx]  = Wn[4096 + idx];
        LWs[idx]  = LW[idx];
    }

    int n0 = blockIdx.x * FN;
    // 3 matrices x 64 rows x 16 float4 = 3072 slots
    #pragma unroll
    for (int p = 0; p < 12; p++) {
        int idx = p * 256 + tid;
        int mat = idx >> 10;
        int slot = idx & 1023;
        int e = slot >> 4, c4 = slot & 15;
        int node = n0 + e;
        const float* srcp = (mat == 0) ? g_A : (mat == 1) ? g_B : feat;
        float* dstp = (mat == 0) ? As : (mat == 1) ? Bs : Fs;
        float4 v = make_float4(0.f, 0.f, 0.f, 0.f);
        if (node < N) v = *(const float4*)&srcp[(size_t)node * 64 + c4 * 4];
        float* hp = &dstp[e * TS + c4 * 4];
        hp[0] = v.x; hp[1] = v.y; hp[2] = v.z; hp[3] = v.w;
    }
    __syncthreads();

    int ty = tid >> 3, tx = tid & 7, jj = tx * 8;     // ty: 0..31, nodes ty and ty+32

    unsigned long long a0 = 0, a1 = 0, a2 = 0, a3 = 0;     // node ty
    unsigned long long b0 = 0, b1 = 0, b2 = 0, b3 = 0;     // node ty+32

    #pragma unroll 4
    for (int k = 0; k < 64; k++) {
        const float* w13 = &W13s[(k << 6) + jj];
        const float* w2  = &W2s[(k << 6) + jj];
        const float* lw  = &LWs[(k << 6) + jj];
        ulonglong2 wA = *reinterpret_cast<const ulonglong2*>(w13);
        ulonglong2 wB = *reinterpret_cast<const ulonglong2*>(w13 + 4);
        ulonglong2 vA = *reinterpret_cast<const ulonglong2*>(w2);
        ulonglong2 vB = *reinterpret_cast<const ulonglong2*>(w2 + 4);
        ulonglong2 uA = *reinterpret_cast<const ulonglong2*>(lw);
        ulonglong2 uB = *reinterpret_cast<const ulonglong2*>(lw + 4);

        float la = As[ty * TS + k];
        float lb = Bs[ty * TS + k];
        float lf = Fs[ty * TS + k];
        unsigned long long la2, lb2, lf2;
        PACK_DUP(la2, la); PACK_DUP(lb2, lb); PACK_DUP(lf2, lf);
        FMA2(a0, la2, wA.x); FMA2(a1, la2, wA.y); FMA2(a2, la2, wB.x); FMA2(a3, la2, wB.y);
        FMA2(a0, lb2, vA.x); FMA2(a1, lb2, vA.y); FMA2(a2, lb2, vB.x); FMA2(a3, lb2, vB.y);
        FMA2(a0, lf2, uA.x); FMA2(a1, lf2, uA.y); FMA2(a2, lf2, uB.x); FMA2(a3, lf2, uB.y);

        float ma = As[(ty + 32) * TS + k];
        float mb = Bs[(ty + 32) * TS + k];
        float mf = Fs[(ty + 32) * TS + k];
        unsigned long long ma2, mb2, mf2;
        PACK_DUP(ma2, ma); PACK_DUP(mb2, mb); PACK_DUP(mf2, mf);
        FMA2(b0, ma2, wA.x); FMA2(b1, ma2, wA.y); FMA2(b2, ma2, wB.x); FMA2(b3, ma2, wB.y);
        FMA2(b0, mb2, vA.x); FMA2(b1, mb2, vA.y); FMA2(b2, mb2, vB.x); FMA2(b3, mb2, vB.y);
        FMA2(b0, mf2, uA.x); FMA2(b1, mf2, uA.y); FMA2(b2, mf2, uB.x); FMA2(b3, mf2, uB.y);
    }

    #pragma unroll
    for (int half = 0; half < 2; half++) {
        int node = n0 + ty + half * 32;
        if (node < N) {
            unsigned long long r0 = half ? b0 : a0;
            unsigned long long r1 = half ? b1 : a1;
            unsigned long long r2 = half ? b2 : a2;
            unsigned long long r3 = half ? b3 : a3;
            float4 c0 = *(const float4*)&g_C[(size_t)node * 64 + jj];
            float4 c1 = *(const float4*)&g_C[(size_t)node * 64 + jj + 4];
            float v0, v1, v2, v3, v4, v5, v6, v7;
            UNPACK2(v0, v1, r0); UNPACK2(v2, v3, r1);
            UNPACK2(v4, v5, r2); UNPACK2(v6, v7, r3);
            float* p = out + (size_t)node * 64 + jj;
            *(float4*)p       = make_float4(v0 + c0.x, v1 + c0.y, v2 + c0.z, v3 + c0.w);
            *(float4*)(p + 4) = make_float4(v4 + c1.x, v5 + c1.y, v6 + c1.z, v7 + c1.w);
        }
    }
}

// -------- launch --------
extern "C" void kernel_launch(void* const* d_in, const int* in_sizes, int n_in,
                              void* d_out, int out_size) {
    const float* feat = (const float*)d_in[0];
    const float* rel  = (const float*)d_in[1];
    const float* Wn   = (const float*)d_in[2];
    const float* LW   = (const float*)d_in[3];
    const int*   src  = (const int*)d_in[4];
    const int*   dst  = (const int*)d_in[5];
    const int*   et   = (const int*)d_in[6];
    float* out = (float*)d_out;

    int E = in_sizes[4];
    int N = in_sizes[0] / 64;

    cudaFuncSetAttribute(k_final, cudaFuncAttributeMaxDynamicSharedMemorySize, FSMEM);

    k_front<<<FB, FT>>>(rel, Wn, src, dst, et, E);                   // 0
    k_agg<<<(NN * 32 + 255) / 256, 256>>>(feat);                     // 1
    k_final<<<(N + FN - 1) / FN, 256, FSMEM>>>(feat, Wn, LW, out, N); // 2
}

// round 14
// speedup vs baseline: 1.8254x; 1.3080x over previous
#include <cuda_runtime.h>
#include <cuda_bf16.h>
#include <cstdint>

#define NN      50000
#define NE      800000
#define NRELS   200
#define FB      148          // front-end blocks (1/SM, co-resident)
#define FT      1024         // front-end threads per block

// -------- scratch (device globals; allocation is forbidden) --------
__device__ int          g_cnt[NN];           // dst degree (re-zeroed by k_agg each call)
__device__ int          g_off[NN + 1];       // global exclusive offsets
__device__ int          g_cur[NN];           // scatter cursors (consumed each call)
__device__ int          g_bsum[FB];
__device__ int          g_boff[FB];
__device__ unsigned int g_key[NE];           // (src | etype<<16) sorted by dst
__device__ float        g_rr[NRELS * 128];   // interleaved (rel, relB) per relation
__device__ float        g_A[NN * 64];
__device__ float        g_B[NN * 64];
__device__ float        g_C[NN * 64];

// grid barrier state: generation flags grow monotonically (no reset needed)
__device__ unsigned int g_bar_cnt[4];
__device__ unsigned int g_bar_flag[4];

// -------- f32x2 helpers --------
#define FMA2(acc, a, b) \
    asm("fma.rn.f32x2 %0, %1, %2, %0;" : "+l"(acc) : "l"(a), "l"(b))
#define ADD2(acc, v) \
    asm("add.rn.f32x2 %0, %0, %1;" : "+l"(acc) : "l"(v))
#define PACK_DUP(h2, h) \
    asm("mov.b64 %0, {%1, %1};" : "=l"(h2) : "f"(h))
#define UNPACK2(lo, hi, v) \
    asm("mov.b64 {%0, %1}, %2;" : "=f"(lo), "=f"(hi) : "l"(v))

// -------- software grid barrier (sense-reversal; FB co-resident blocks) --------
__device__ __forceinline__ void grid_sync(int i) {
    __threadfence();
    __syncthreads();
    if (threadIdx.x == 0) {
        unsigned sense = *(volatile unsigned*)&g_bar_flag[i];
        unsigned old = atomicAdd(&g_bar_cnt[i], 1u);
        if (old == (unsigned)(FB - 1)) {
            g_bar_cnt[i] = 0;
            __threadfence();
            atomicAdd(&g_bar_flag[i], 1u);   // release (generation++)
        } else {
            while (*(volatile unsigned*)&g_bar_flag[i] == sense) __nanosleep(64);
        }
        __threadfence();
    }
    __syncthreads();
}

// -------- K1: fused front-end: relB+hist -> scan -> boff -> globalize -> scatter --------
__global__ __launch_bounds__(FT) void k_front(const float* __restrict__ rel,
                                              const float* __restrict__ Wn,
                                              const int* __restrict__ src,
                                              const int* __restrict__ dst,
                                              const int* __restrict__ et, int E) {
    __shared__ int tmp[FT];
    int b = blockIdx.x, tid = threadIdx.x;
    int gid = b * FT + tid;
    const int nthr = FB * FT;

    // ---- phase 0: relB table + dst degree histogram ----
    if (gid < NRELS * 64) {
        int t = gid >> 6, j = gid & 63;
        float s = 0.0f;
        #pragma unroll 8
        for (int k = 0; k < 64; k++)
            s += rel[t * 64 + k] * (Wn[k * 64 + j] + Wn[(192 + k) * 64 + j]);
        int base = t * 128 + (j >> 1) * 4 + (j & 1);
        g_rr[base]     = rel[t * 64 + j];
        g_rr[base + 2] = s;
    }
    int n4 = E >> 2;
    {
        const int4* d4 = (const int4*)dst;
        for (int j = gid; j < n4; j += nthr) {
            int4 v = d4[j];
            atomicAdd(&g_cnt[v.x], 1);
            atomicAdd(&g_cnt[v.y], 1);
            atomicAdd(&g_cnt[v.z], 1);
            atomicAdd(&g_cnt[v.w], 1);
        }
        if (gid < (E & 3)) atomicAdd(&g_cnt[dst[(n4 << 2) + gid]], 1);
    }
    grid_sync(0);

    // ---- phase 1a: per-block local exclusive scan over FT counts ----
    int v = (gid < NN) ? g_cnt[gid] : 0;
    tmp[tid] = v;
    __syncthreads();
    #pragma unroll
    for (int d = 1; d < FT; d <<= 1) {
        int t = (tid >= d) ? tmp[tid - d] : 0;
        __syncthreads();
        tmp[tid] += t;
        __syncthreads();
    }
    int loc = tmp[tid] - v;               // local exclusive offset (register)
    if (tid == FT - 1) g_bsum[b] = tmp[FT - 1];
    grid_sync(1);

    // ---- phase 1b: block 0 scans the FB block sums ----
    if (b == 0) {
        int vv = (tid < FB) ? g_bsum[tid] : 0;
        if (tid < 256) tmp[tid] = vv;
        __syncthreads();
        #pragma unroll
        for (int d = 1; d < 256; d <<= 1) {
            int t = (tid >= d && tid < 256) ? tmp[tid - d] : 0;
            __syncthreads();
            if (tid < 256) tmp[tid] += t;
            __syncthreads();
        }
        if (tid < FB) g_boff[tid] = tmp[tid] - vv;
        if (tid == 0) g_off[NN] = E;
    }
    grid_sync(2);

    // ---- phase 1c: globalize offsets + init cursors ----
    if (gid < NN) {
        int off = loc + g_boff[b];
        g_off[gid] = off;
        g_cur[gid] = off;
    }
    grid_sync(3);

    // ---- phase 2: counting-sort scatter by dst ----
    {
        const int4* s4 = (const int4*)src;
        const int4* d4 = (const int4*)dst;
        const int4* t4 = (const int4*)et;
        for (int j = gid; j < n4; j += nthr) {
            int4 s = s4[j];
            int4 d = d4[j];
            int4 t = t4[j];
            int p0 = atomicAdd(&g_cur[d.x], 1);
            int p1 = atomicAdd(&g_cur[d.y], 1);
            int p2 = atomicAdd(&g_cur[d.z], 1);
            int p3 = atomicAdd(&g_cur[d.w], 1);
            g_key[p0] = (unsigned)s.x | ((unsigned)t.x << 16);
            g_key[p1] = (unsigned)s.y | ((unsigned)t.y << 16);
            g_key[p2] = (unsigned)s.z | ((unsigned)t.z << 16);
            g_key[p3] = (unsigned)s.w | ((unsigned)t.w << 16);
        }
        if (gid < (E & 3)) {
            int e = (n4 << 2) + gid;
            int p = atomicAdd(&g_cur[dst[e]], 1);
            g_key[p] = (unsigned)src[e] | ((unsigned)et[e] << 16);
        }
    }
}

// -------- K2: per-dst aggregation (warp/node, 2-edge unroll, packed f32x2 math) --------
__global__ __launch_bounds__(256) void k_agg(const float* __restrict__ feat) {
    int w = (blockIdx.x * 256 + threadIdx.x) >> 5;
    if (w >= NN) return;
    int lane = threadIdx.x & 31;
    int beg = g_off[w], end = g_off[w + 1];
    if (lane == 0) g_cnt[w] = 0;      // re-zero for next replay (deterministic)

    const unsigned long long* f8  = (const unsigned long long*)feat;   // 32 packs / row
    const ulonglong2*         rr8 = (const ulonglong2*)g_rr;           // .x=(r pair) .y=(relB pair)

    unsigned long long A0 = 0ull, B0 = 0ull, C0 = 0ull;
    unsigned long long A1 = 0ull, B1 = 0ull, C1 = 0ull;

    int i = beg;
    if ((end - beg) & 1) {                        // peel odd edge
        unsigned k = g_key[i++];
        unsigned long long h = f8[(k & 0xffffu) * 32 + lane];
        ulonglong2 q = rr8[(k >> 16) * 32 + lane];
        ADD2(A0, h);
        FMA2(B0, h, q.x);
        ADD2(C0, q.y);
    }
    if (i < end) {
        unsigned k0 = g_key[i];
        unsigned k1 = g_key[i + 1];
        for (; i < end; i += 2) {
            bool more = (i + 2) < end;
            unsigned n0 = more ? g_key[i + 2] : k0;
            unsigned n1 = more ? g_key[i + 3] : k1;

            unsigned long long h0 = f8[(k0 & 0xffffu) * 32 + lane];
            ulonglong2 q0 = rr8[(k0 >> 16) * 32 + lane];
            unsigned long long h1 = f8[(k1 & 0xffffu) * 32 + lane];
            ulonglong2 q1 = rr8[(k1 >> 16) * 32 + lane];

            ADD2(A0, h0);
            FMA2(B0, h0, q0.x);
            ADD2(C0, q0.y);

            ADD2(A1, h1);
            FMA2(B1, h1, q1.x);
            ADD2(C1, q1.y);

            k0 = n0; k1 = n1;
        }
    }

    float inv = 1.0f / fmaxf((float)(end - beg), 1.0f);
    float ax0, ay0, ax1, ay1, bx0, by0, bx1, by1, cx0, cy0, cx1, cy1;
    UNPACK2(ax0, ay0, A0); UNPACK2(ax1, ay1, A1);
    UNPACK2(bx0, by0, B0); UNPACK2(bx1, by1, B1);
    UNPACK2(cx0, cy0, C0); UNPACK2(cx1, cy1, C1);

    int o = w * 32 + lane;
    ((float2*)g_A)[o] = make_float2((ax0 + ax1) * inv, (ay0 + ay1) * inv);
    ((float2*)g_B)[o] = make_float2((bx0 + bx1) * inv, (by0 + by1) * inv);
    ((float2*)g_C)[o] = make_float2((cx0 + cx1) * inv, (cy0 + cy1) * inv);
}

// -------- K3: out = A@W13 + B@W2 + C + feat@LW --------
// 128 nodes / block, 256 threads, 4 nodes per thread; TS=68 keeps float4 alignment
#define TS 68
#define FN 128
#define FSMEM ((3 * 4096 + 3 * FN * TS) * 4)

__global__ __launch_bounds__(256) void k_final(const float* __restrict__ feat,
                                               const float* __restrict__ Wn,
                                               const float* __restrict__ LW,
                                               float* __restrict__ out, int N) {
    extern __shared__ float smem[];
    float* W13s = smem;                 // 4096
    float* W2s  = smem + 4096;          // 4096
    float* LWs  = smem + 8192;          // 4096
    float* As   = smem + 12288;         // FN*68
    float* Bs   = As + FN * TS;
    float* Fs   = Bs + FN * TS;

    int tid = threadIdx.x;
    for (int idx = tid; idx < 4096; idx += 256) {
        W13s[idx] = Wn[idx] + Wn[8192 + idx];
        W2s[idx]  = Wn[4096 + idx];
        LWs[idx]  = LW[idx];
    }

    int n0 = blockIdx.x * FN;
    // 3 matrices x 128 rows x 16 float4 = 6144 slots
    #pragma unroll
    for (int p = 0; p < 24; p++) {
        int idx = p * 256 + tid;
        int mat = idx >> 11;
        int slot = idx & 2047;
        int e = slot >> 4, c4 = slot & 15;
        int node = n0 + e;
        const float* srcp = (mat == 0) ? g_A : (mat == 1) ? g_B : feat;
        float* dstp = (mat == 0) ? As : (mat == 1) ? Bs : Fs;
        float4 v = make_float4(0.f, 0.f, 0.f, 0.f);
        if (node < N) v = *(const float4*)&srcp[(size_t)node * 64 + c4 * 4];
        *(float4*)&dstp[e * TS + c4 * 4] = v;     // TS=68 -> 16B aligned
    }
    __syncthreads();

    int ty = tid >> 3, tx = tid & 7, jj = tx * 8;   // nodes ty, ty+32, ty+64, ty+96

    unsigned long long acc[4][4];
    #pragma unroll
    for (int n = 0; n < 4; n++)
        #pragma unroll
        for (int j = 0; j < 4; j++) acc[n][j] = 0ull;

    #pragma unroll 2
    for (int k4 = 0; k4 < 16; k4++) {
        float4 a4[4], b4[4], f4[4];
        #pragma unroll
        for (int n = 0; n < 4; n++) {
            int row = (ty + 32 * n) * TS + k4 * 4;
            a4[n] = *(const float4*)&As[row];
            b4[n] = *(const float4*)&Bs[row];
            f4[n] = *(const float4*)&Fs[row];
        }

        #define KSTEP(u, comp)                                                        \
        {                                                                             \
            int k = k4 * 4 + u;                                                       \
            const float* w13 = &W13s[(k << 6) + jj];                                  \
            const float* w2  = &W2s[(k << 6) + jj];                                   \
            const float* lw  = &LWs[(k << 6) + jj];                                   \
            ulonglong2 wA = *reinterpret_cast<const ulonglong2*>(w13);                \
            ulonglong2 wB = *reinterpret_cast<const ulonglong2*>(w13 + 4);            \
            ulonglong2 vA = *reinterpret_cast<const ulonglong2*>(w2);                 \
            ulonglong2 vB = *reinterpret_cast<const ulonglong2*>(w2 + 4);             \
            ulonglong2 uA = *reinterpret_cast<const ulonglong2*>(lw);                 \
            ulonglong2 uB = *reinterpret_cast<const ulonglong2*>(lw + 4);             \
            _Pragma("unroll")                                                         \
            for (int n = 0; n < 4; n++) {                                             \
                unsigned long long la2, lb2, lf2;                                     \
                PACK_DUP(la2, a4[n].comp);                                            \
                PACK_DUP(lb2, b4[n].comp);                                            \
                PACK_DUP(lf2, f4[n].comp);                                            \
                FMA2(acc[n][0], la2, wA.x); FMA2(acc[n][1], la2, wA.y);               \
                FMA2(acc[n][2], la2, wB.x); FMA2(acc[n][3], la2, wB.y);               \
                FMA2(acc[n][0], lb2, vA.x); FMA2(acc[n][1], lb2, vA.y);               \
                FMA2(acc[n][2], lb2, vB.x); FMA2(acc[n][3], lb2, vB.y);               \
                FMA2(acc[n][0], lf2, uA.x); FMA2(acc[n][1], lf2, uA.y);               \
                FMA2(acc[n][2], lf2, uB.x); FMA2(acc[n][3], lf2, uB.y);               \
            }                                                                         \
        }
        KSTEP(0, x) KSTEP(1, y) KSTEP(2, z) KSTEP(3, w)
        #undef KSTEP
    }

    #pragma unroll
    for (int n = 0; n < 4; n++) {
        int node = n0 + ty + 32 * n;
        if (node < N) {
            float4 c0 = *(const float4*)&g_C[(size_t)node * 64 + jj];
            float4 c1 = *(const float4*)&g_C[(size_t)node * 64 + jj + 4];
            float v0, v1, v2, v3, v4, v5, v6, v7;
            UNPACK2(v0, v1, acc[n][0]); UNPACK2(v2, v3, acc[n][1]);
            UNPACK2(v4, v5, acc[n][2]); UNPACK2(v6, v7, acc[n][3]);
            float* p = out + (size_t)node * 64 + jj;
            *(float4*)p       = make_float4(v0 + c0.x, v1 + c0.y, v2 + c0.z, v3 + c0.w);
            *(float4*)(p + 4) = make_float4(v4 + c1.x, v5 + c1.y, v6 + c1.z, v7 + c1.w);
        }
    }
}

// -------- launch --------
extern "C" void kernel_launch(void* const* d_in, const int* in_sizes, int n_in,
                              void* d_out, int out_size) {
    const float* feat = (const float*)d_in[0];
    const float* rel  = (const float*)d_in[1];
    const float* Wn   = (const float*)d_in[2];
    const float* LW   = (const float*)d_in[3];
    const int*   src  = (const int*)d_in[4];
    const int*   dst  = (const int*)d_in[5];
    const int*   et   = (const int*)d_in[6];
    float* out = (float*)d_out;

    int E = in_sizes[4];
    int N = in_sizes[0] / 64;

    cudaFuncSetAttribute(k_final, cudaFuncAttributeMaxDynamicSharedMemorySize, FSMEM);

    k_front<<<FB, FT>>>(rel, Wn, src, dst, et, E);                    // 0
    k_agg<<<(NN * 32 + 255) / 256, 256>>>(feat);                      // 1
    k_final<<<(N + FN - 1) / FN, 256, FSMEM>>>(feat, Wn, LW, out, N); // 2
}